// round 3
// baseline (speedup 1.0000x reference)
#include <cuda_runtime.h>
#include <cstdint>
#include <cstddef>

// GRU decoder: T=1024, B=256, H=512, O=64.
// Inputs: code_vec, target, w_ih, w_hh, b_ih, b_hh, w_out, b_out.
// Output: outputs [T,B,O] fp32, then h_last [1,B,H].

#define TT 1024
#define BB 256
#define HH 512
#define OO 64

#define GM 32            // hidden-tile groups (16 units each)
#define GB 4             // batch groups (64 each)
#define NBLK (GM * GB)   // 128 blocks, 1/SM -> co-resident (barrier-safe)
#define NTHR 256

__device__ float g_h[(TT + 1) * HH * BB];   // h states [t][k][b]
__device__ float g_xT[TT * OO * BB];        // x transposed [t][o][b], tf32-rounded
__device__ unsigned g_count;
__device__ volatile unsigned g_gen;

__device__ __forceinline__ float tf32r(float x) {
    uint32_t u;
    asm("cvt.rna.tf32.f32 %0, %1;" : "=r"(u) : "f"(x));
    return __uint_as_float(u);
}

__device__ __forceinline__ void mma8(float* d, const float4 a4, float b0, float b1) {
    uint32_t A0 = __float_as_uint(a4.x), A1 = __float_as_uint(a4.y);
    uint32_t A2 = __float_as_uint(a4.z), A3 = __float_as_uint(a4.w);
    uint32_t B0 = __float_as_uint(b0), B1 = __float_as_uint(b1);
    asm volatile(
        "mma.sync.aligned.m16n8k8.row.col.f32.tf32.tf32.f32 "
        "{%0,%1,%2,%3}, {%4,%5,%6,%7}, {%8,%9}, {%0,%1,%2,%3};\n"
        : "+f"(d[0]), "+f"(d[1]), "+f"(d[2]), "+f"(d[3])
        : "r"(A0), "r"(A1), "r"(A2), "r"(A3), "r"(B0), "r"(B1));
}

// ---------------- prep kernels ----------------
__global__ void prep_h0(const float* __restrict__ code_vec) {
    if (blockIdx.x == 0 && threadIdx.x == 0) { g_count = 0u; g_gen = 0u; }
    int idx = blockIdx.x * 256 + threadIdx.x;
    if (idx < HH * BB) {
        int k = idx >> 8, b = idx & 255;
        g_h[k * BB + b] = code_vec[b * HH + k];
    }
}

__global__ void prep_x(const float* __restrict__ target) {
    int t = blockIdx.x;
    for (int i = threadIdx.x; i < OO * BB; i += 256) {
        int o = i >> 8, b = i & 255;
        float v = (t == 0) ? 0.f : target[((size_t)(t - 1) * BB + b) * OO + o];
        g_xT[(size_t)t * OO * BB + i] = tf32r(v);
    }
}

// ---------------- persistent recurrence kernel ----------------
// SMEM floats: Wp packed weights [72 kstep][3 gate][32 lane]float4 = 27648 f (110KB)
//              buf double-buffered h slab 2 x [128][68] = 17408 f (69.6KB)
//              sx  x operand [64 o][68] = 4352 f (17.4KB)
#define SM_BUF 27648
#define SM_SX  (27648 + 17408)
#define SM_TOTF (27648 + 17408 + 4352)   // 49408 f = 197632 B

__global__ __launch_bounds__(NTHR, 1) void gru_persistent(
    const float* __restrict__ w_ih, const float* __restrict__ w_hh,
    const float* __restrict__ b_ih, const float* __restrict__ b_hh) {
    extern __shared__ float sm[];
    float4* Wp = reinterpret_cast<float4*>(sm);
    float* sx = sm + SM_SX;

    const int tid = threadIdx.x;
    const int mg = blockIdx.x & 31;
    const int bg = blockIdx.x >> 5;
    const int hid0 = mg * 16;
    const int b0 = bg * 64;
    const int lane = tid & 31, w = tid >> 5;
    const int qr = lane >> 2, qc = lane & 3;
    const int n0 = w * 8;                       // this warp's batch-col group

    // ---- one-time: pack weights into A-fragment layout ----
    for (int idx = tid; idx < 72 * 96; idx += NTHR) {
        int kstep = idx / 96, r = idx % 96;
        int g = r >> 5, ln = r & 31;
        int lqr = ln >> 2, lqc = ln & 3;
        int row0 = g * HH + hid0 + lqr;
        int c0 = kstep * 8 + lqc, c1 = c0 + 4;
        float4 v;
        v.x = tf32r(c0 < HH ? w_hh[(size_t)row0 * HH + c0] : w_ih[(size_t)row0 * OO + c0 - HH]);
        v.y = tf32r(c0 < HH ? w_hh[(size_t)(row0 + 8) * HH + c0] : w_ih[(size_t)(row0 + 8) * OO + c0 - HH]);
        v.z = tf32r(c1 < HH ? w_hh[(size_t)row0 * HH + c1] : w_ih[(size_t)row0 * OO + c1 - HH]);
        v.w = tf32r(c1 < HH ? w_hh[(size_t)(row0 + 8) * HH + c1] : w_ih[(size_t)(row0 + 8) * OO + c1 - HH]);
        Wp[idx] = v;
    }

    // ---- biases for this thread's two output rows ----
    float br[2], bz[2], bin[2], bhn[2];
    #pragma unroll
    for (int rr = 0; rr < 2; ++rr) {
        int u = hid0 + qr + rr * 8;
        br[rr] = b_ih[u] + b_hh[u];
        bz[rr] = b_ih[HH + u] + b_hh[HH + u];
        bin[rr] = b_ih[2 * HH + u];
        bhn[rr] = b_hh[2 * HH + u];
    }

    for (int t = 0; t < TT; ++t) {
        const float* hsrc = g_h + (size_t)t * HH * BB;
        const float* xsrc = g_xT + (size_t)t * OO * BB;

        // ---- prologue: LDG x + slab0 + h_prev ----
        float4 X[4];
        #pragma unroll
        for (int j = 0; j < 4; ++j) {
            int idx = j * NTHR + tid;
            int row = idx >> 4, c4 = (idx & 15) << 2;
            X[j] = *reinterpret_cast<const float4*>(xsrc + (size_t)row * BB + b0 + c4);
        }
        float4 R[8];
        #pragma unroll
        for (int j = 0; j < 8; ++j) {
            int idx = j * NTHR + tid;
            int row = idx >> 4, c4 = (idx & 15) << 2;
            R[j] = *reinterpret_cast<const float4*>(hsrc + (size_t)row * BB + b0 + c4);
        }
        float hprev[4];
        #pragma unroll
        for (int e = 0; e < 4; ++e) {
            int row = qr + ((e & 2) ? 8 : 0);
            int col = n0 + qc * 2 + (e & 1);
            hprev[e] = hsrc[(size_t)(hid0 + row) * BB + b0 + col];
        }
        // stage x + slab0
        #pragma unroll
        for (int j = 0; j < 4; ++j) {
            int idx = j * NTHR + tid;
            int row = idx >> 4, c4 = (idx & 15) << 2;
            *reinterpret_cast<float4*>(&sx[row * 68 + c4]) = X[j];
        }
        #pragma unroll
        for (int j = 0; j < 8; ++j) {
            int idx = j * NTHR + tid;
            int row = idx >> 4, c4 = (idx & 15) << 2;
            float4 v = R[j];
            v.x = tf32r(v.x); v.y = tf32r(v.y); v.z = tf32r(v.z); v.w = tf32r(v.w);
            *reinterpret_cast<float4*>(&sm[SM_BUF + row * 68 + c4]) = v;
        }

        float acc[3][4] = {}, accX[4] = {};

        #pragma unroll
        for (int slab = 0; slab < 4; ++slab) {
            // prefetch next slab into regs
            if (slab < 3) {
                #pragma unroll
                for (int j = 0; j < 8; ++j) {
                    int idx = j * NTHR + tid;
                    int row = idx >> 4, c4 = (idx & 15) << 2;
                    R[j] = *reinterpret_cast<const float4*>(
                        hsrc + (size_t)((slab + 1) * 128 + row) * BB + b0 + c4);
                }
            }
            __syncthreads();  // buf[slab&1] (and sx) ready

            const float* bufc = sm + SM_BUF + (slab & 1) * (128 * 68);
            #pragma unroll
            for (int c = 0; c < 16; ++c) {
                const int kk = c * 8;
                const int gk = slab * 16 + c;
                float bf0 = bufc[(kk + qc) * 68 + n0 + qr];
                float bf1 = bufc[(kk + 4 + qc) * 68 + n0 + qr];
                #pragma unroll
                for (int g = 0; g < 3; ++g)
                    mma8(acc[g], Wp[(gk * 3 + g) * 32 + lane], bf0, bf1);
            }
            if (slab == 3) {
                #pragma unroll
                for (int kx = 0; kx < 8; ++kx) {
                    float bf0 = sx[(kx * 8 + qc) * 68 + n0 + qr];
                    float bf1 = sx[(kx * 8 + 4 + qc) * 68 + n0 + qr];
                    const int gk = 64 + kx;
                    mma8(acc[0], Wp[(gk * 3 + 0) * 32 + lane], bf0, bf1);
                    mma8(acc[1], Wp[(gk * 3 + 1) * 32 + lane], bf0, bf1);
                    mma8(accX, Wp[(gk * 3 + 2) * 32 + lane], bf0, bf1);
                }
            }
            // stage next slab into the other buffer (safe: other region; all warps
            // finished reading it before the sync above)
            if (slab < 3) {
                float* bufn = sm + SM_BUF + ((slab + 1) & 1) * (128 * 68);
                #pragma unroll
                for (int j = 0; j < 8; ++j) {
                    int idx = j * NTHR + tid;
                    int row = idx >> 4, c4 = (idx & 15) << 2;
                    float4 v = R[j];
                    v.x = tf32r(v.x); v.y = tf32r(v.y); v.z = tf32r(v.z); v.w = tf32r(v.w);
                    *reinterpret_cast<float4*>(&bufn[row * 68 + c4]) = v;
                }
            }
        }

        // ---- in-register GRU epilogue ----
        float* hdst = g_h + (size_t)(t + 1) * HH * BB;
        float hnew[4];
        #pragma unroll
        for (int e = 0; e < 4; ++e) {
            int rr = e >> 1;
            float pr = acc[0][e] + br[rr];
            float pz = acc[1][e] + bz[rr];
            float r = 1.f / (1.f + __expf(-pr));
            float z = 1.f / (1.f + __expf(-pz));
            float n = tanhf(accX[e] + bin[rr] + r * (acc[2][e] + bhn[rr]));
            hnew[e] = (1.f - z) * n + z * hprev[e];
        }
        #pragma unroll
        for (int rr = 0; rr < 2; ++rr) {
            int u = hid0 + qr + rr * 8;
            float2 v = make_float2(hnew[rr * 2], hnew[rr * 2 + 1]);
            *reinterpret_cast<float2*>(&hdst[(size_t)u * BB + b0 + n0 + qc * 2]) = v;
        }

        // ---- grid barrier (128 co-resident blocks) ----
        __syncthreads();
        if (tid == 0) {
            __threadfence();
            unsigned a = atomicAdd(&g_count, 1u) + 1u;
            if (a == (unsigned)NBLK * (unsigned)(t + 1)) {
                __threadfence();
                g_gen = (unsigned)(t + 1);
            } else {
                while (g_gen < (unsigned)(t + 1)) {}
                __threadfence();
            }
        }
        __syncthreads();
    }
}

// ---------------- output projection y_t = h_{t+1} @ w_out^T + b_out ----------------
__global__ __launch_bounds__(256) void out_kernel(float* __restrict__ out,
                                                  const float* __restrict__ w_out,
                                                  const float* __restrict__ b_out) {
    extern __shared__ float sm[];
    float* h_sh = sm;                     // [512][72]
    float* Wsl = sm + 512 * 72;           // [64][68]
    float* y_sh = Wsl + 64 * 68;          // [64 b][65]
    const int tid = threadIdx.x;
    const int b0 = blockIdx.x * 64;
    const int t = blockIdx.y;

    const float* hsrc = &g_h[(size_t)(t + 1) * HH * BB];
    for (int i = tid; i < 512 * 64; i += 256) {
        int k = i >> 6, b = i & 63;
        h_sh[k * 72 + b] = tf32r(hsrc[(size_t)k * BB + b0 + b]);
    }

    const int w = tid >> 5, lane = tid & 31;
    const int mh = w & 3, nh = w >> 2;
    const int qr = lane >> 2, qc = lane & 3;
    float acc[4][4] = {};

    for (int s = 0; s < 8; ++s) {
        __syncthreads();
        for (int i = tid; i < 64 * 16; i += 256) {
            int r = i >> 4, c4 = (i & 15) * 4;
            float4 v = *reinterpret_cast<const float4*>(&w_out[(size_t)r * HH + s * 64 + c4]);
            v.x = tf32r(v.x); v.y = tf32r(v.y); v.z = tf32r(v.z); v.w = tf32r(v.w);
            *reinterpret_cast<float4*>(&Wsl[r * 68 + c4]) = v;
        }
        __syncthreads();
        #pragma unroll
        for (int c = 0; c < 8; ++c) {
            const int kk = c * 8;
            float4 a4;
            a4.x = Wsl[(mh * 16 + qr) * 68 + kk + qc];
            a4.y = Wsl[(mh * 16 + qr + 8) * 68 + kk + qc];
            a4.z = Wsl[(mh * 16 + qr) * 68 + kk + 4 + qc];
            a4.w = Wsl[(mh * 16 + qr + 8) * 68 + kk + 4 + qc];
            const int krow = s * 64 + kk;
            #pragma unroll
            for (int n8 = 0; n8 < 4; ++n8) {
                int nn = (nh * 4 + n8) * 8;
                float bf0 = h_sh[(krow + qc) * 72 + nn + qr];
                float bf1 = h_sh[(krow + 4 + qc) * 72 + nn + qr];
                mma8(acc[n8], a4, bf0, bf1);
            }
        }
    }

    __syncthreads();
    #pragma unroll
    for (int n8 = 0; n8 < 4; ++n8)
        #pragma unroll
        for (int e = 0; e < 4; ++e) {
            int row = mh * 16 + qr + ((e & 2) ? 8 : 0);
            int col = (nh * 4 + n8) * 8 + qc * 2 + (e & 1);
            y_sh[col * 65 + row] = acc[n8][e];
        }
    __syncthreads();

    float* yo = &out[((size_t)t * BB + b0) * OO];
    for (int i = tid; i < 64 * 64; i += 256) {
        int b = i >> 6, o = i & 63;
        yo[b * OO + o] = y_sh[b * 65 + o] + b_out[o];
    }
}

__global__ void hlast_kernel(float* __restrict__ out) {
    int idx = blockIdx.x * 256 + threadIdx.x;
    if (idx < BB * HH) {
        int b = idx >> 9, k = idx & 511;
        out[idx] = g_h[(size_t)TT * HH * BB + (size_t)k * BB + b];
    }
}

// ---------------- launch ----------------
extern "C" void kernel_launch(void* const* d_in, const int* in_sizes, int n_in,
                              void* d_out, int out_size) {
    const float* code_vec = (const float*)d_in[0];
    const float* target   = (const float*)d_in[1];
    const float* w_ih     = (const float*)d_in[2];
    const float* w_hh     = (const float*)d_in[3];
    const float* b_ih     = (const float*)d_in[4];
    const float* b_hh     = (const float*)d_in[5];
    const float* w_out    = (const float*)d_in[6];
    const float* b_out    = (const float*)d_in[7];
    float* out = (float*)d_out;

    const size_t smem_step = SM_TOTF * sizeof(float);                                // 197632 B
    const size_t smem_out = (size_t)(512 * 72 + 64 * 68 + 64 * 65) * sizeof(float);  // 181504 B
    cudaFuncSetAttribute(gru_persistent, cudaFuncAttributeMaxDynamicSharedMemorySize, (int)smem_step);
    cudaFuncSetAttribute(out_kernel, cudaFuncAttributeMaxDynamicSharedMemorySize, (int)smem_out);

    prep_h0<<<(HH * BB + 255) / 256, 256>>>(code_vec);
    prep_x<<<TT, 256>>>(target);
    gru_persistent<<<NBLK, NTHR, smem_step>>>(w_ih, w_hh, b_ih, b_hh);
    out_kernel<<<dim3(4, TT), 256, smem_out>>>(out, w_out, b_out);
    hlast_kernel<<<(BB * HH + 255) / 256, 256>>>(out + (size_t)TT * BB * OO);
}

// round 4
// speedup vs baseline: 1.0013x; 1.0013x over previous
#include <cuda_runtime.h>
#include <cstdint>
#include <cstddef>

// GRU decoder: T=1024, B=256, H=512, O=64.
// Inputs: code_vec, target, w_ih, w_hh, b_ih, b_hh, w_out, b_out.
// Output: outputs [T,B,O] fp32, then h_last [1,B,H].

#define TT 1024
#define BB 256
#define HH 512
#define OO 64

#define GM 32            // hidden-tile groups (16 units each)
#define GB 4             // batch groups (64 each)
#define NBLK (GM * GB)   // 128 blocks, 1/SM -> co-resident (barrier-safe)
#define NTHR 256

__device__ float g_h[(TT + 1) * HH * BB];   // h states [t][k][b]
__device__ float g_xT[TT * OO * BB];        // x transposed [t][o][b], tf32-rounded
__device__ unsigned g_count;
__device__ volatile unsigned g_gen;

__device__ __forceinline__ float tf32r(float x) {
    uint32_t u;
    asm("cvt.rna.tf32.f32 %0, %1;" : "=r"(u) : "f"(x));
    return __uint_as_float(u);
}

__device__ __forceinline__ void mma8(float* d, const float4 a4, float b0, float b1) {
    uint32_t A0 = __float_as_uint(a4.x), A1 = __float_as_uint(a4.y);
    uint32_t A2 = __float_as_uint(a4.z), A3 = __float_as_uint(a4.w);
    uint32_t B0 = __float_as_uint(b0), B1 = __float_as_uint(b1);
    asm volatile(
        "mma.sync.aligned.m16n8k8.row.col.f32.tf32.tf32.f32 "
        "{%0,%1,%2,%3}, {%4,%5,%6,%7}, {%8,%9}, {%0,%1,%2,%3};\n"
        : "+f"(d[0]), "+f"(d[1]), "+f"(d[2]), "+f"(d[3])
        : "r"(A0), "r"(A1), "r"(A2), "r"(A3), "r"(B0), "r"(B1));
}

// ---------------- prep kernels ----------------
__global__ void prep_h0(const float* __restrict__ code_vec) {
    if (blockIdx.x == 0 && threadIdx.x == 0) { g_count = 0u; g_gen = 0u; }
    int idx = blockIdx.x * 256 + threadIdx.x;
    if (idx < HH * BB) {
        int k = idx >> 8, b = idx & 255;
        g_h[k * BB + b] = code_vec[b * HH + k];
    }
}

__global__ void prep_x(const float* __restrict__ target) {
    int t = blockIdx.x;
    for (int i = threadIdx.x; i < OO * BB; i += 256) {
        int o = i >> 8, b = i & 255;
        float v = (t == 0) ? 0.f : target[((size_t)(t - 1) * BB + b) * OO + o];
        g_xT[(size_t)t * OO * BB + i] = tf32r(v);
    }
}

// ---------------- persistent recurrence kernel ----------------
// SMEM floats: Wp packed weights [72 kstep][3 gate][32 lane]float4 = 27648 f (110KB)
//              buf double-buffered h slab 2 x [128][68] = 17408 f (69.6KB)
//              sx  x operand [64 o][68] = 4352 f (17.4KB)
#define SM_BUF 27648
#define SM_SX  (27648 + 17408)
#define SM_TOTF (27648 + 17408 + 4352)   // 49408 f = 197632 B

__global__ __launch_bounds__(NTHR, 1) void gru_persistent(
    const float* __restrict__ w_ih, const float* __restrict__ w_hh,
    const float* __restrict__ b_ih, const float* __restrict__ b_hh) {
    extern __shared__ float sm[];
    float4* Wp = reinterpret_cast<float4*>(sm);
    float* sx = sm + SM_SX;

    const int tid = threadIdx.x;
    const int mg = blockIdx.x & 31;
    const int bg = blockIdx.x >> 5;
    const int hid0 = mg * 16;
    const int b0 = bg * 64;
    const int lane = tid & 31, w = tid >> 5;
    const int qr = lane >> 2, qc = lane & 3;
    const int n0 = w * 8;                       // this warp's batch-col group

    // ---- one-time: pack weights into A-fragment layout ----
    for (int idx = tid; idx < 72 * 96; idx += NTHR) {
        int kstep = idx / 96, r = idx % 96;
        int g = r >> 5, ln = r & 31;
        int lqr = ln >> 2, lqc = ln & 3;
        int row0 = g * HH + hid0 + lqr;
        int c0 = kstep * 8 + lqc, c1 = c0 + 4;
        float4 v;
        v.x = tf32r(c0 < HH ? w_hh[(size_t)row0 * HH + c0] : w_ih[(size_t)row0 * OO + c0 - HH]);
        v.y = tf32r(c0 < HH ? w_hh[(size_t)(row0 + 8) * HH + c0] : w_ih[(size_t)(row0 + 8) * OO + c0 - HH]);
        v.z = tf32r(c1 < HH ? w_hh[(size_t)row0 * HH + c1] : w_ih[(size_t)row0 * OO + c1 - HH]);
        v.w = tf32r(c1 < HH ? w_hh[(size_t)(row0 + 8) * HH + c1] : w_ih[(size_t)(row0 + 8) * OO + c1 - HH]);
        Wp[idx] = v;
    }

    // ---- biases for this thread's two output rows ----
    float br[2], bz[2], bin[2], bhn[2];
    #pragma unroll
    for (int rr = 0; rr < 2; ++rr) {
        int u = hid0 + qr + rr * 8;
        br[rr] = b_ih[u] + b_hh[u];
        bz[rr] = b_ih[HH + u] + b_hh[HH + u];
        bin[rr] = b_ih[2 * HH + u];
        bhn[rr] = b_hh[2 * HH + u];
    }

    for (int t = 0; t < TT; ++t) {
        const float* hsrc = g_h + (size_t)t * HH * BB;
        const float* xsrc = g_xT + (size_t)t * OO * BB;

        // ---- prologue: LDG x + slab0 + h_prev ----
        float4 X[4];
        #pragma unroll
        for (int j = 0; j < 4; ++j) {
            int idx = j * NTHR + tid;
            int row = idx >> 4, c4 = (idx & 15) << 2;
            X[j] = *reinterpret_cast<const float4*>(xsrc + (size_t)row * BB + b0 + c4);
        }
        float4 R[8];
        #pragma unroll
        for (int j = 0; j < 8; ++j) {
            int idx = j * NTHR + tid;
            int row = idx >> 4, c4 = (idx & 15) << 2;
            R[j] = *reinterpret_cast<const float4*>(hsrc + (size_t)row * BB + b0 + c4);
        }
        float hprev[4];
        #pragma unroll
        for (int e = 0; e < 4; ++e) {
            int row = qr + ((e & 2) ? 8 : 0);
            int col = n0 + qc * 2 + (e & 1);
            hprev[e] = hsrc[(size_t)(hid0 + row) * BB + b0 + col];
        }
        // stage x + slab0
        #pragma unroll
        for (int j = 0; j < 4; ++j) {
            int idx = j * NTHR + tid;
            int row = idx >> 4, c4 = (idx & 15) << 2;
            *reinterpret_cast<float4*>(&sx[row * 68 + c4]) = X[j];
        }
        #pragma unroll
        for (int j = 0; j < 8; ++j) {
            int idx = j * NTHR + tid;
            int row = idx >> 4, c4 = (idx & 15) << 2;
            float4 v = R[j];
            v.x = tf32r(v.x); v.y = tf32r(v.y); v.z = tf32r(v.z); v.w = tf32r(v.w);
            *reinterpret_cast<float4*>(&sm[SM_BUF + row * 68 + c4]) = v;
        }

        float acc[3][4] = {}, accX[4] = {};

        #pragma unroll
        for (int slab = 0; slab < 4; ++slab) {
            // prefetch next slab into regs
            if (slab < 3) {
                #pragma unroll
                for (int j = 0; j < 8; ++j) {
                    int idx = j * NTHR + tid;
                    int row = idx >> 4, c4 = (idx & 15) << 2;
                    R[j] = *reinterpret_cast<const float4*>(
                        hsrc + (size_t)((slab + 1) * 128 + row) * BB + b0 + c4);
                }
            }
            __syncthreads();  // buf[slab&1] (and sx) ready

            const float* bufc = sm + SM_BUF + (slab & 1) * (128 * 68);
            #pragma unroll
            for (int c = 0; c < 16; ++c) {
                const int kk = c * 8;
                const int gk = slab * 16 + c;
                float bf0 = bufc[(kk + qc) * 68 + n0 + qr];
                float bf1 = bufc[(kk + 4 + qc) * 68 + n0 + qr];
                #pragma unroll
                for (int g = 0; g < 3; ++g)
                    mma8(acc[g], Wp[(gk * 3 + g) * 32 + lane], bf0, bf1);
            }
            if (slab == 3) {
                #pragma unroll
                for (int kx = 0; kx < 8; ++kx) {
                    float bf0 = sx[(kx * 8 + qc) * 68 + n0 + qr];
                    float bf1 = sx[(kx * 8 + 4 + qc) * 68 + n0 + qr];
                    const int gk = 64 + kx;
                    mma8(acc[0], Wp[(gk * 3 + 0) * 32 + lane], bf0, bf1);
                    mma8(acc[1], Wp[(gk * 3 + 1) * 32 + lane], bf0, bf1);
                    mma8(accX, Wp[(gk * 3 + 2) * 32 + lane], bf0, bf1);
                }
            }
            // stage next slab into the other buffer (safe: other region; all warps
            // finished reading it before the sync above)
            if (slab < 3) {
                float* bufn = sm + SM_BUF + ((slab + 1) & 1) * (128 * 68);
                #pragma unroll
                for (int j = 0; j < 8; ++j) {
                    int idx = j * NTHR + tid;
                    int row = idx >> 4, c4 = (idx & 15) << 2;
                    float4 v = R[j];
                    v.x = tf32r(v.x); v.y = tf32r(v.y); v.z = tf32r(v.z); v.w = tf32r(v.w);
                    *reinterpret_cast<float4*>(&bufn[row * 68 + c4]) = v;
                }
            }
        }

        // ---- in-register GRU epilogue ----
        float* hdst = g_h + (size_t)(t + 1) * HH * BB;
        float hnew[4];
        #pragma unroll
        for (int e = 0; e < 4; ++e) {
            int rr = e >> 1;
            float pr = acc[0][e] + br[rr];
            float pz = acc[1][e] + bz[rr];
            float r = 1.f / (1.f + __expf(-pr));
            float z = 1.f / (1.f + __expf(-pz));
            float n = tanhf(accX[e] + bin[rr] + r * (acc[2][e] + bhn[rr]));
            hnew[e] = (1.f - z) * n + z * hprev[e];
        }
        #pragma unroll
        for (int rr = 0; rr < 2; ++rr) {
            int u = hid0 + qr + rr * 8;
            float2 v = make_float2(hnew[rr * 2], hnew[rr * 2 + 1]);
            *reinterpret_cast<float2*>(&hdst[(size_t)u * BB + b0 + n0 + qc * 2]) = v;
        }

        // ---- grid barrier (128 co-resident blocks) ----
        __syncthreads();
        if (tid == 0) {
            __threadfence();
            unsigned a = atomicAdd(&g_count, 1u) + 1u;
            if (a == (unsigned)NBLK * (unsigned)(t + 1)) {
                __threadfence();
                g_gen = (unsigned)(t + 1);
            } else {
                while (g_gen < (unsigned)(t + 1)) {}
                __threadfence();
            }
        }
        __syncthreads();
    }
}

// ---------------- output projection y_t = h_{t+1} @ w_out^T + b_out ----------------
__global__ __launch_bounds__(256) void out_kernel(float* __restrict__ out,
                                                  const float* __restrict__ w_out,
                                                  const float* __restrict__ b_out) {
    extern __shared__ float sm[];
    float* h_sh = sm;                     // [512][72]
    float* Wsl = sm + 512 * 72;           // [64][68]
    float* y_sh = Wsl + 64 * 68;          // [64 b][65]
    const int tid = threadIdx.x;
    const int b0 = blockIdx.x * 64;
    const int t = blockIdx.y;

    const float* hsrc = &g_h[(size_t)(t + 1) * HH * BB];
    for (int i = tid; i < 512 * 64; i += 256) {
        int k = i >> 6, b = i & 63;
        h_sh[k * 72 + b] = tf32r(hsrc[(size_t)k * BB + b0 + b]);
    }

    const int w = tid >> 5, lane = tid & 31;
    const int mh = w & 3, nh = w >> 2;
    const int qr = lane >> 2, qc = lane & 3;
    float acc[4][4] = {};

    for (int s = 0; s < 8; ++s) {
        __syncthreads();
        for (int i = tid; i < 64 * 16; i += 256) {
            int r = i >> 4, c4 = (i & 15) * 4;
            float4 v = *reinterpret_cast<const float4*>(&w_out[(size_t)r * HH + s * 64 + c4]);
            v.x = tf32r(v.x); v.y = tf32r(v.y); v.z = tf32r(v.z); v.w = tf32r(v.w);
            *reinterpret_cast<float4*>(&Wsl[r * 68 + c4]) = v;
        }
        __syncthreads();
        #pragma unroll
        for (int c = 0; c < 8; ++c) {
            const int kk = c * 8;
            float4 a4;
            a4.x = Wsl[(mh * 16 + qr) * 68 + kk + qc];
            a4.y = Wsl[(mh * 16 + qr + 8) * 68 + kk + qc];
            a4.z = Wsl[(mh * 16 + qr) * 68 + kk + 4 + qc];
            a4.w = Wsl[(mh * 16 + qr + 8) * 68 + kk + 4 + qc];
            const int krow = s * 64 + kk;
            #pragma unroll
            for (int n8 = 0; n8 < 4; ++n8) {
                int nn = (nh * 4 + n8) * 8;
                float bf0 = h_sh[(krow + qc) * 72 + nn + qr];
                float bf1 = h_sh[(krow + 4 + qc) * 72 + nn + qr];
                mma8(acc[n8], a4, bf0, bf1);
            }
        }
    }

    __syncthreads();
    #pragma unroll
    for (int n8 = 0; n8 < 4; ++n8)
        #pragma unroll
        for (int e = 0; e < 4; ++e) {
            int row = mh * 16 + qr + ((e & 2) ? 8 : 0);
            int col = (nh * 4 + n8) * 8 + qc * 2 + (e & 1);
            y_sh[col * 65 + row] = acc[n8][e];
        }
    __syncthreads();

    float* yo = &out[((size_t)t * BB + b0) * OO];
    for (int i = tid; i < 64 * 64; i += 256) {
        int b = i >> 6, o = i & 63;
        yo[b * OO + o] = y_sh[b * 65 + o] + b_out[o];
    }
}

__global__ void hlast_kernel(float* __restrict__ out) {
    int idx = blockIdx.x * 256 + threadIdx.x;
    if (idx < BB * HH) {
        int b = idx >> 9, k = idx & 511;
        out[idx] = g_h[(size_t)TT * HH * BB + (size_t)k * BB + b];
    }
}

// ---------------- launch ----------------
extern "C" void kernel_launch(void* const* d_in, const int* in_sizes, int n_in,
                              void* d_out, int out_size) {
    const float* code_vec = (const float*)d_in[0];
    const float* target   = (const float*)d_in[1];
    const float* w_ih     = (const float*)d_in[2];
    const float* w_hh     = (const float*)d_in[3];
    const float* b_ih     = (const float*)d_in[4];
    const float* b_hh     = (const float*)d_in[5];
    const float* w_out    = (const float*)d_in[6];
    const float* b_out    = (const float*)d_in[7];
    float* out = (float*)d_out;

    const size_t smem_step = SM_TOTF * sizeof(float);                                // 197632 B
    const size_t smem_out = (size_t)(512 * 72 + 64 * 68 + 64 * 65) * sizeof(float);  // 181504 B
    cudaFuncSetAttribute(gru_persistent, cudaFuncAttributeMaxDynamicSharedMemorySize, (int)smem_step);
    cudaFuncSetAttribute(out_kernel, cudaFuncAttributeMaxDynamicSharedMemorySize, (int)smem_out);

    prep_h0<<<(HH * BB + 255) / 256, 256>>>(code_vec);
    prep_x<<<TT, 256>>>(target);
    gru_persistent<<<NBLK, NTHR, smem_step>>>(w_ih, w_hh, b_ih, b_hh);
    out_kernel<<<dim3(4, TT), 256, smem_out>>>(out, w_out, b_out);
    hlast_kernel<<<(BB * HH + 255) / 256, 256>>>(out + (size_t)TT * BB * OO);
}

// round 5
// speedup vs baseline: 1.2438x; 1.2422x over previous
#include <cuda_runtime.h>
#include <cstdint>
#include <cstddef>

#define TT 1024
#define BB 256
#define HH 512
#define OO 64
#define NBLK 128
#define NTHR 256

__device__ float g_h[(TT + 1) * HH * BB];   // [t][k][b]
__device__ float g_xT[TT * OO * BB];        // [t][o][b], tf32-rounded
__device__ unsigned g_count;
__device__ volatile unsigned g_gen;

__device__ __forceinline__ float tf32r(float x) {
    uint32_t u;
    asm("cvt.rna.tf32.f32 %0, %1;" : "=r"(u) : "f"(x));
    return __uint_as_float(u);
}

__device__ __forceinline__ void mma8(float* d, const float4 a4, float b0, float b1) {
    uint32_t A0 = __float_as_uint(a4.x), A1 = __float_as_uint(a4.y);
    uint32_t A2 = __float_as_uint(a4.z), A3 = __float_as_uint(a4.w);
    uint32_t B0 = __float_as_uint(b0), B1 = __float_as_uint(b1);
    asm volatile(
        "mma.sync.aligned.m16n8k8.row.col.f32.tf32.tf32.f32 "
        "{%0,%1,%2,%3}, {%4,%5,%6,%7}, {%8,%9}, {%0,%1,%2,%3};\n"
        : "+f"(d[0]), "+f"(d[1]), "+f"(d[2]), "+f"(d[3])
        : "r"(A0), "r"(A1), "r"(A2), "r"(A3), "r"(B0), "r"(B1));
}

__device__ __forceinline__ void cpa16(uint32_t dst, const void* src) {
    asm volatile("cp.async.ca.shared.global [%0], [%1], 16;\n" :: "r"(dst), "l"(src));
}

__global__ void prep_h0(const float* __restrict__ code_vec) {
    if (blockIdx.x == 0 && threadIdx.x == 0) { g_count = 0u; g_gen = 0u; }
    int idx = blockIdx.x * 256 + threadIdx.x;
    if (idx < HH * BB) {
        int k = idx >> 8, b = idx & 255;
        g_h[k * BB + b] = code_vec[b * HH + k];
    }
}

__global__ void prep_x(const float* __restrict__ target) {
    int t = blockIdx.x;
    for (int i = threadIdx.x; i < OO * BB; i += 256) {
        int o = i >> 8, b = i & 255;
        float v = (t == 0) ? 0.f : target[((size_t)(t - 1) * BB + b) * OO + o];
        g_xT[(size_t)t * OO * BB + i] = tf32r(v);
    }
}

// SMEM: Wp 27648f | buf 2x[128][72]=18432f (overlaid by exchange) | sx [64][72]=4608f
#define SM_BUF 27648
#define SM_SX  46080
#define SM_TOTF 50688   // 202752 B

__global__ __launch_bounds__(NTHR, 1) void gru_persistent(
    const float* __restrict__ w_ih, const float* __restrict__ w_hh,
    const float* __restrict__ b_ih, const float* __restrict__ b_hh) {
    extern __shared__ float sm[];
    float4* Wp4 = reinterpret_cast<float4*>(sm);
    float* buf = sm + SM_BUF;
    float* sx = sm + SM_SX;
    float* xch = sm + SM_BUF;

    const int tid = threadIdx.x;
    const int hid0 = (blockIdx.x & 31) * 16;
    const int b0 = (blockIdx.x >> 5) * 64;
    const int lane = tid & 31, w = tid >> 5;
    const int kh = w >> 2, nq = w & 3;       // 2 K-halves x 4 n-quarters
    const int qr = lane >> 2, qc = lane & 3;
    const int n0 = nq * 16;

    const uint32_t smem_b = (uint32_t)__cvta_generic_to_shared(sm);
    const uint32_t buf_b = smem_b + SM_BUF * 4u;
    const uint32_t sx_b = smem_b + SM_SX * 4u;

    // pack weights into A-fragment layout (validated R1/R3)
    for (int idx = tid; idx < 72 * 96; idx += NTHR) {
        int kstep = idx / 96, r = idx % 96;
        int g = r >> 5, ln = r & 31;
        int lqr = ln >> 2, lqc = ln & 3;
        int row0 = g * HH + hid0 + lqr;
        int c0 = kstep * 8 + lqc, c1 = c0 + 4;
        float4 v;
        v.x = tf32r(c0 < HH ? w_hh[(size_t)row0 * HH + c0] : w_ih[(size_t)row0 * OO + c0 - HH]);
        v.y = tf32r(c0 < HH ? w_hh[(size_t)(row0 + 8) * HH + c0] : w_ih[(size_t)(row0 + 8) * OO + c0 - HH]);
        v.z = tf32r(c1 < HH ? w_hh[(size_t)row0 * HH + c1] : w_ih[(size_t)row0 * OO + c1 - HH]);
        v.w = tf32r(c1 < HH ? w_hh[(size_t)(row0 + 8) * HH + c1] : w_ih[(size_t)(row0 + 8) * OO + c1 - HH]);
        Wp4[idx] = v;
    }

    // epilogue thread mapping: rows krb+4*r2, col bcol
    const int krb = tid >> 6, bcol = tid & 63;
    float brv[4], bzv[4], binv[4], bhnv[4];
    #pragma unroll
    for (int r2 = 0; r2 < 4; ++r2) {
        int u = hid0 + krb + 4 * r2;
        brv[r2] = b_ih[u] + b_hh[u];
        bzv[r2] = b_ih[HH + u] + b_hh[HH + u];
        binv[r2] = b_ih[2 * HH + u];
        bhnv[r2] = b_hh[2 * HH + u];
    }
    // exchange read constants
    const int rnq = bcol >> 4, rj = (bcol >> 3) & 1, rqc = (bcol & 7) >> 1, re1 = bcol & 1;

    for (int t = 0; t < TT; ++t) {
        const float* hsrc = g_h + (size_t)t * HH * BB;
        const float* xsrc = g_xT + (size_t)t * OO * BB;

        float hprev[4];
        #pragma unroll
        for (int r2 = 0; r2 < 4; ++r2)
            hprev[r2] = hsrc[(size_t)(hid0 + krb + 4 * r2) * BB + b0 + bcol];

        // slab0 + x via cp.async
        #pragma unroll
        for (int j = 0; j < 8; ++j) {
            int idx = j * NTHR + tid;
            int row = idx >> 4, c4 = (idx & 15) << 2;
            cpa16(buf_b + (uint32_t)((row * 72 + c4) * 4), hsrc + (size_t)row * BB + b0 + c4);
        }
        #pragma unroll
        for (int j = 0; j < 4; ++j) {
            int idx = j * NTHR + tid;
            int row = idx >> 4, c4 = (idx & 15) << 2;
            cpa16(sx_b + (uint32_t)((row * 72 + c4) * 4), xsrc + (size_t)row * BB + b0 + c4);
        }
        asm volatile("cp.async.commit_group;\n");

        float acc[3][2][4] = {}, accX[2][4] = {};

        #pragma unroll
        for (int s = 0; s < 4; ++s) {
            asm volatile("cp.async.wait_group 0;\n");
            __syncthreads();  // slab s in smem; all warps done with buf[(s-1)&1]
            if (s < 3) {      // prefetch slab s+1 (other half; disjoint from readers)
                const float* src = hsrc + (size_t)(128 * (s + 1)) * BB + b0;
                uint32_t dstb = buf_b + (uint32_t)(((s + 1) & 1) * 9216 * 4);
                #pragma unroll
                for (int j = 0; j < 8; ++j) {
                    int idx = j * NTHR + tid;
                    int row = idx >> 4, c4 = (idx & 15) << 2;
                    cpa16(dstb + (uint32_t)((row * 72 + c4) * 4), src + (size_t)row * BB + c4);
                }
                asm volatile("cp.async.commit_group;\n");
            }
            const float* bs = buf + (s & 1) * 9216;
            #pragma unroll
            for (int c = 0; c < 8; ++c) {
                const int gk = s * 16 + kh * 8 + c;
                const int kk = (kh * 8 + c) * 8;
                float bf0[2], bf1[2];
                #pragma unroll
                for (int j = 0; j < 2; ++j) {
                    bf0[j] = tf32r(bs[(kk + qc) * 72 + n0 + j * 8 + qr]);
                    bf1[j] = tf32r(bs[(kk + 4 + qc) * 72 + n0 + j * 8 + qr]);
                }
                #pragma unroll
                for (int g = 0; g < 3; ++g) {
                    float4 a4 = Wp4[(gk * 3 + g) * 32 + lane];
                    mma8(acc[g][0], a4, bf0[0], bf1[0]);
                    mma8(acc[g][1], a4, bf0[1], bf1[1]);
                }
            }
        }
        // x-path (pre-rounded); gate-n x-part separate
        #pragma unroll
        for (int c2 = 0; c2 < 4; ++c2) {
            const int gk = 64 + kh * 4 + c2;
            const int kk = (kh * 4 + c2) * 8;
            float bf0[2], bf1[2];
            #pragma unroll
            for (int j = 0; j < 2; ++j) {
                bf0[j] = sx[(kk + qc) * 72 + n0 + j * 8 + qr];
                bf1[j] = sx[(kk + 4 + qc) * 72 + n0 + j * 8 + qr];
            }
            float4 a0 = Wp4[(gk * 3 + 0) * 32 + lane];
            float4 a1 = Wp4[(gk * 3 + 1) * 32 + lane];
            float4 a2 = Wp4[(gk * 3 + 2) * 32 + lane];
            #pragma unroll
            for (int j = 0; j < 2; ++j) {
                mma8(acc[0][j], a0, bf0[j], bf1[j]);
                mma8(acc[1][j], a1, bf0[j], bf1[j]);
                mma8(accX[j], a2, bf0[j], bf1[j]);
            }
        }

        __syncthreads();  // done reading buf/sx; overlay exchange
        // per-thread slot, stride 33 (conflict-free writes)
        {
            float* slot = xch + tid * 33;
            #pragma unroll
            for (int g = 0; g < 3; ++g)
                #pragma unroll
                for (int j = 0; j < 2; ++j)
                    #pragma unroll
                    for (int e = 0; e < 4; ++e)
                        slot[g * 8 + j * 4 + e] = acc[g][j][e];
            #pragma unroll
            for (int j = 0; j < 2; ++j)
                #pragma unroll
                for (int e = 0; e < 4; ++e)
                    slot[24 + j * 4 + e] = accX[j][e];
        }
        __syncthreads();

        float* hdst = g_h + (size_t)(t + 1) * HH * BB;
        #pragma unroll
        for (int r2 = 0; r2 < 4; ++r2) {
            const int kr = krb + 4 * r2;
            const int rqr = kr & 7, re = ((kr >> 3) << 1) | re1;
            const int lidx = rqr * 4 + rqc;
            float q[4] = {0.f, 0.f, 0.f, 0.f};
            #pragma unroll
            for (int hh2 = 0; hh2 < 2; ++hh2) {
                const float* sl = xch + ((hh2 * 4 + rnq) * 32 + lidx) * 33 + rj * 4 + re;
                q[0] += sl[0];
                q[1] += sl[8];
                q[2] += sl[16];
                q[3] += sl[24];
            }
            float r = 1.f / (1.f + __expf(-(q[0] + brv[r2])));
            float z = 1.f / (1.f + __expf(-(q[1] + bzv[r2])));
            float n = tanhf(q[3] + binv[r2] + r * (q[2] + bhnv[r2]));
            hdst[(size_t)(hid0 + kr) * BB + b0 + bcol] = (1.f - z) * n + z * hprev[r2];
        }

        __syncthreads();
        if (tid == 0) {
            __threadfence();
            unsigned a = atomicAdd(&g_count, 1u) + 1u;
            if (a == (unsigned)NBLK * (unsigned)(t + 1)) {
                __threadfence();
                g_gen = (unsigned)(t + 1);
            } else {
                while (g_gen < (unsigned)(t + 1)) {}
                __threadfence();
            }
        }
        __syncthreads();
    }
}

// out: y_t = h_{t+1} @ w_out^T + b_out.  2 blocks/SM, float4 staging, K in 2 halves.
#define OH_W 18432
#define OH_Y 22784
#define OH_TOT 26944   // 107776 B

__global__ __launch_bounds__(256, 2) void out_kernel(float* __restrict__ out,
                                                     const float* __restrict__ w_out,
                                                     const float* __restrict__ b_out) {
    extern __shared__ float sm[];
    float* h_sh = sm;            // [256][72]
    float* Wsl = sm + OH_W;      // [64][68]
    float* y_sh = sm + OH_Y;     // [64][65]
    const int tid = threadIdx.x;
    const int b0 = blockIdx.x * 64;
    const int t = blockIdx.y;

    const float* hsrc = &g_h[(size_t)(t + 1) * HH * BB];
    const int w = tid >> 5, lane = tid & 31;
    const int mh = w & 3, nh = w >> 2;
    const int qr = lane >> 2, qc = lane & 3;
    float acc[4][4] = {};

    for (int khf = 0; khf < 2; ++khf) {
        __syncthreads();
        for (int i = tid; i < 256 * 16; i += 256) {
            int k = i >> 4, c4 = (i & 15) * 4;
            float4 v = *reinterpret_cast<const float4*>(
                hsrc + (size_t)(khf * 256 + k) * BB + b0 + c4);
            v.x = tf32r(v.x); v.y = tf32r(v.y); v.z = tf32r(v.z); v.w = tf32r(v.w);
            *reinterpret_cast<float4*>(&h_sh[k * 72 + c4]) = v;
        }
        for (int s = 0; s < 4; ++s) {
            if (khf | s) __syncthreads();
            for (int i = tid; i < 64 * 16; i += 256) {
                int r = i >> 4, c4 = (i & 15) * 4;
                float4 v = *reinterpret_cast<const float4*>(
                    &w_out[(size_t)r * HH + khf * 256 + s * 64 + c4]);
                v.x = tf32r(v.x); v.y = tf32r(v.y); v.z = tf32r(v.z); v.w = tf32r(v.w);
                *reinterpret_cast<float4*>(&Wsl[r * 68 + c4]) = v;
            }
            __syncthreads();
            #pragma unroll
            for (int c = 0; c < 8; ++c) {
                const int kk = c * 8;
                float4 a4;
                a4.x = Wsl[(mh * 16 + qr) * 68 + kk + qc];
                a4.y = Wsl[(mh * 16 + qr + 8) * 68 + kk + qc];
                a4.z = Wsl[(mh * 16 + qr) * 68 + kk + 4 + qc];
                a4.w = Wsl[(mh * 16 + qr + 8) * 68 + kk + 4 + qc];
                const int krow = s * 64 + kk;
                #pragma unroll
                for (int n8 = 0; n8 < 4; ++n8) {
                    int nn = (nh * 4 + n8) * 8;
                    float bf0 = h_sh[(krow + qc) * 72 + nn + qr];
                    float bf1 = h_sh[(krow + 4 + qc) * 72 + nn + qr];
                    mma8(acc[n8], a4, bf0, bf1);
                }
            }
        }
    }

    __syncthreads();
    #pragma unroll
    for (int n8 = 0; n8 < 4; ++n8)
        #pragma unroll
        for (int e = 0; e < 4; ++e) {
            int row = mh * 16 + qr + ((e & 2) ? 8 : 0);
            int col = (nh * 4 + n8) * 8 + qc * 2 + (e & 1);
            y_sh[col * 65 + row] = acc[n8][e];
        }
    __syncthreads();

    float* yo = &out[((size_t)t * BB + b0) * OO];
    for (int i = tid; i < 64 * 64; i += 256) {
        int b = i >> 6, o = i & 63;
        yo[b * OO + o] = y_sh[b * 65 + o] + b_out[o];
    }
}

__global__ void hlast_kernel(float* __restrict__ out) {
    int idx = blockIdx.x * 256 + threadIdx.x;
    if (idx < BB * HH) {
        int b = idx >> 9, k = idx & 511;
        out[idx] = g_h[(size_t)TT * HH * BB + (size_t)k * BB + b];
    }
}

extern "C" void kernel_launch(void* const* d_in, const int* in_sizes, int n_in,
                              void* d_out, int out_size) {
    const float* code_vec = (const float*)d_in[0];
    const float* target   = (const float*)d_in[1];
    const float* w_ih     = (const float*)d_in[2];
    const float* w_hh     = (const float*)d_in[3];
    const float* b_ih     = (const float*)d_in[4];
    const float* b_hh     = (const float*)d_in[5];
    const float* w_out    = (const float*)d_in[6];
    const float* b_out    = (const float*)d_in[7];
    float* out = (float*)d_out;

    const size_t smem_step = SM_TOTF * sizeof(float);   // 202752
    const size_t smem_out = OH_TOT * sizeof(float);     // 107776
    cudaFuncSetAttribute(gru_persistent, cudaFuncAttributeMaxDynamicSharedMemorySize, (int)smem_step);
    cudaFuncSetAttribute(out_kernel, cudaFuncAttributeMaxDynamicSharedMemorySize, (int)smem_out);

    prep_h0<<<(HH * BB + 255) / 256, 256>>>(code_vec);
    prep_x<<<TT, 256>>>(target);
    gru_persistent<<<NBLK, NTHR, smem_step>>>(w_ih, w_hh, b_ih, b_hh);
    out_kernel<<<dim3(4, TT), 256, smem_out>>>(out, w_out, b_out);
    hlast_kernel<<<(BB * HH + 255) / 256, 256>>>(out + (size_t)TT * BB * OO);
}

// round 6
// speedup vs baseline: 1.3123x; 1.0551x over previous
#include <cuda_runtime.h>
#include <cstdint>
#include <cstddef>

#define TT 1024
#define BB 256
#define HH 512
#define OO 64
#define NBLK 128
#define NTHR 256

__device__ float g_hbuf[2][HH * BB];    // rotating h slots [k][b] (1 MB, L2-resident)
__device__ float g_xT[TT * OO * BB];    // [t][o][b], tf32-rounded
__device__ unsigned g_count;

__device__ __forceinline__ float tf32r(float x) {
    uint32_t u;
    asm("cvt.rna.tf32.f32 %0, %1;" : "=r"(u) : "f"(x));
    return __uint_as_float(u);
}

__device__ __forceinline__ void mma8(float* d, const float4 a4, float b0, float b1) {
    uint32_t A0 = __float_as_uint(a4.x), A1 = __float_as_uint(a4.y);
    uint32_t A2 = __float_as_uint(a4.z), A3 = __float_as_uint(a4.w);
    uint32_t B0 = __float_as_uint(b0), B1 = __float_as_uint(b1);
    asm volatile(
        "mma.sync.aligned.m16n8k8.row.col.f32.tf32.tf32.f32 "
        "{%0,%1,%2,%3}, {%4,%5,%6,%7}, {%8,%9}, {%0,%1,%2,%3};\n"
        : "+f"(d[0]), "+f"(d[1]), "+f"(d[2]), "+f"(d[3])
        : "r"(A0), "r"(A1), "r"(A2), "r"(A3), "r"(B0), "r"(B1));
}

__device__ __forceinline__ void cpa16(uint32_t dst, const void* src) {
    asm volatile("cp.async.ca.shared.global [%0], [%1], 16;\n" :: "r"(dst), "l"(src));
}

__global__ void prep_h0(const float* __restrict__ code_vec) {
    if (blockIdx.x == 0 && threadIdx.x == 0) g_count = 0u;
    int idx = blockIdx.x * 256 + threadIdx.x;
    if (idx < HH * BB) {
        int k = idx >> 8, b = idx & 255;
        g_hbuf[0][k * BB + b] = code_vec[b * HH + k];
    }
}

__global__ void prep_x(const float* __restrict__ target) {
    int t = blockIdx.x;
    for (int i = threadIdx.x; i < OO * BB; i += 256) {
        int o = i >> 8, b = i & 255;
        float v = (t == 0) ? 0.f : target[((size_t)(t - 1) * BB + b) * OO + o];
        g_xT[(size_t)t * OO * BB + i] = tf32r(v);
    }
}

__global__ void dummy_k(int x) { if (x == 12345 && threadIdx.x > 1024) g_count = 1; }

// SMEM floats: Wp 27648 | buf 2x[128][72]=18432 (exchange overlays) | sx [64][72]=4608
//              wo [2][512]=1024 | yx [4][2][64]=512
#define SM_BUF 27648
#define SM_SX  46080
#define SM_WO  50688
#define SM_YX  51712
#define SM_TOTF 52224   // 208896 B

__global__ __launch_bounds__(NTHR, 1) void gru_persistent(
    float* __restrict__ out,
    const float* __restrict__ w_ih, const float* __restrict__ w_hh,
    const float* __restrict__ b_ih, const float* __restrict__ b_hh,
    const float* __restrict__ w_out, const float* __restrict__ b_out) {
    extern __shared__ float sm[];
    float4* Wp4 = reinterpret_cast<float4*>(sm);
    float* buf = sm + SM_BUF;
    float* sx = sm + SM_SX;
    float* wo = sm + SM_WO;
    float* yx = sm + SM_YX;
    float* xch = buf;

    const int tid = threadIdx.x;
    const int mg = blockIdx.x & 31;
    const int hid0 = mg * 16;
    const int b0 = (blockIdx.x >> 5) * 64;
    const int lane = tid & 31, w = tid >> 5;
    const int ks = w >> 1, nh = w & 1;      // 4 K-slices x 2 n-halves
    const int qr = lane >> 2, qc = lane & 3;
    const int n0 = nh * 32;
    const int orow0 = mg * 2;               // this block's 2 output rows

    const uint32_t smem_b = (uint32_t)__cvta_generic_to_shared(sm);
    const uint32_t buf_b = smem_b + SM_BUF * 4u;
    const uint32_t sx_b = smem_b + SM_SX * 4u;

    // pack weights into A-fragment layout (validated R1/R3/R5)
    for (int idx = tid; idx < 72 * 96; idx += NTHR) {
        int kstep = idx / 96, r = idx % 96;
        int g = r >> 5, ln = r & 31;
        int lqr = ln >> 2, lqc = ln & 3;
        int row0 = g * HH + hid0 + lqr;
        int c0 = kstep * 8 + lqc, c1 = c0 + 4;
        float4 v;
        v.x = tf32r(c0 < HH ? w_hh[(size_t)row0 * HH + c0] : w_ih[(size_t)row0 * OO + c0 - HH]);
        v.y = tf32r(c0 < HH ? w_hh[(size_t)(row0 + 8) * HH + c0] : w_ih[(size_t)(row0 + 8) * OO + c0 - HH]);
        v.z = tf32r(c1 < HH ? w_hh[(size_t)row0 * HH + c1] : w_ih[(size_t)row0 * OO + c1 - HH]);
        v.w = tf32r(c1 < HH ? w_hh[(size_t)(row0 + 8) * HH + c1] : w_ih[(size_t)(row0 + 8) * OO + c1 - HH]);
        Wp4[idx] = v;
    }
    // resident w_out slice [2][512], raw fp32
    for (int i = tid; i < 256; i += NTHR) {
        int o2 = i >> 7, c4 = (i & 127) * 4;
        *reinterpret_cast<float4*>(&wo[o2 * 512 + c4]) =
            *reinterpret_cast<const float4*>(&w_out[(size_t)(orow0 + o2) * HH + c4]);
    }

    const int krb = tid >> 6, bcol = tid & 63;
    float brv[4], bzv[4], binv[4], bhnv[4];
    #pragma unroll
    for (int r2 = 0; r2 < 4; ++r2) {
        int u = hid0 + krb + 4 * r2;
        brv[r2] = b_ih[u] + b_hh[u];
        bzv[r2] = b_ih[HH + u] + b_hh[HH + u];
        binv[r2] = b_ih[2 * HH + u];
        bhnv[r2] = b_hh[2 * HH + u];
    }
    // exchange-read constants
    const int xnh = bcol >> 5, xj = (bcol & 31) >> 3, xqc = (bcol & 7) >> 1, xel = bcol & 1;
    const float yb = (tid < 128) ? b_out[orow0 + (tid >> 6)] : 0.f;
    const int ykb = (tid >> 6) * 32;

    // h_prev carried in registers (this block wrote these values last step)
    float hprev[4];
    #pragma unroll
    for (int r2 = 0; r2 < 4; ++r2)
        hprev[r2] = g_hbuf[0][(size_t)(hid0 + krb + 4 * r2) * BB + b0 + bcol];

    for (int t = 0; t < TT; ++t) {
        const float* hsrc = g_hbuf[t & 1];
        const float* xsrc = g_xT + (size_t)t * OO * BB;

        #pragma unroll
        for (int j = 0; j < 8; ++j) {
            int idx = j * NTHR + tid;
            int row = idx >> 4, c4 = (idx & 15) << 2;
            cpa16(buf_b + (uint32_t)((row * 72 + c4) * 4), hsrc + (size_t)row * BB + b0 + c4);
        }
        #pragma unroll
        for (int j = 0; j < 4; ++j) {
            int idx = j * NTHR + tid;
            int row = idx >> 4, c4 = (idx & 15) << 2;
            cpa16(sx_b + (uint32_t)((row * 72 + c4) * 4), xsrc + (size_t)row * BB + b0 + c4);
        }
        asm volatile("cp.async.commit_group;\n");

        float acc[3][4][4] = {}, accX[4][4] = {};
        float yp0 = 0.f, yp1 = 0.f;

        #pragma unroll
        for (int s = 0; s < 4; ++s) {
            asm volatile("cp.async.wait_group 0;\n");
            __syncthreads();
            if (s < 3) {
                const float* src = hsrc + (size_t)(128 * (s + 1)) * BB + b0;
                uint32_t dstb = buf_b + (uint32_t)(((s + 1) & 1) * 9216 * 4);
                #pragma unroll
                for (int j = 0; j < 8; ++j) {
                    int idx = j * NTHR + tid;
                    int row = idx >> 4, c4 = (idx & 15) << 2;
                    cpa16(dstb + (uint32_t)((row * 72 + c4) * 4), src + (size_t)row * BB + c4);
                }
                asm volatile("cp.async.commit_group;\n");
            }
            const float* bs = buf + (s & 1) * 9216;
            // y[t-1] partial from staged raw h[t] (full fp32)
            #pragma unroll
            for (int i = 0; i < 32; ++i) {
                float hv = bs[(ykb + i) * 72 + bcol];
                int k = s * 128 + ykb + i;
                yp0 = fmaf(hv, wo[k], yp0);
                yp1 = fmaf(hv, wo[512 + k], yp1);
            }
            // gates: warp ks handles 4 ksteps of this slab
            #pragma unroll
            for (int c = 0; c < 4; ++c) {
                const int gk = s * 16 + ks * 4 + c;
                const int kk = (ks * 4 + c) * 8;
                float bf0[4], bf1[4];
                #pragma unroll
                for (int j = 0; j < 4; ++j) {
                    bf0[j] = tf32r(bs[(kk + qc) * 72 + n0 + j * 8 + qr]);
                    bf1[j] = tf32r(bs[(kk + 4 + qc) * 72 + n0 + j * 8 + qr]);
                }
                #pragma unroll
                for (int g = 0; g < 3; ++g) {
                    float4 a4 = Wp4[(gk * 3 + g) * 32 + lane];
                    #pragma unroll
                    for (int j = 0; j < 4; ++j) mma8(acc[g][j], a4, bf0[j], bf1[j]);
                }
            }
        }
        // x-path (pre-rounded); gate-n x-part separate
        #pragma unroll
        for (int c2 = 0; c2 < 2; ++c2) {
            const int gk = 64 + ks * 2 + c2;
            const int kk = (ks * 2 + c2) * 8;
            float bf0[4], bf1[4];
            #pragma unroll
            for (int j = 0; j < 4; ++j) {
                bf0[j] = sx[(kk + qc) * 72 + n0 + j * 8 + qr];
                bf1[j] = sx[(kk + 4 + qc) * 72 + n0 + j * 8 + qr];
            }
            float4 a0 = Wp4[(gk * 3 + 0) * 32 + lane];
            float4 a1 = Wp4[(gk * 3 + 1) * 32 + lane];
            float4 a2 = Wp4[(gk * 3 + 2) * 32 + lane];
            #pragma unroll
            for (int j = 0; j < 4; ++j) {
                mma8(acc[0][j], a0, bf0[j], bf1[j]);
                mma8(acc[1][j], a1, bf0[j], bf1[j]);
                mma8(accX[j], a2, bf0[j], bf1[j]);
            }
        }

        __syncthreads();  // done reading buf/sx; overlay exchange
        {
            float* slot = xch + tid * 65;   // per-thread slot, stride 65 -> conflict-free
            #pragma unroll
            for (int g = 0; g < 3; ++g)
                #pragma unroll
                for (int j = 0; j < 4; ++j)
                    #pragma unroll
                    for (int e = 0; e < 4; ++e)
                        slot[g * 16 + j * 4 + e] = acc[g][j][e];
            #pragma unroll
            for (int j = 0; j < 4; ++j)
                #pragma unroll
                for (int e = 0; e < 4; ++e)
                    slot[48 + j * 4 + e] = accX[j][e];
        }
        yx[((tid >> 6) * 2 + 0) * 64 + bcol] = yp0;
        yx[((tid >> 6) * 2 + 1) * 64 + bcol] = yp1;
        __syncthreads();

        float* hdst = g_hbuf[(t + 1) & 1];
        #pragma unroll
        for (int r2 = 0; r2 < 4; ++r2) {
            const int kr = krb + 4 * r2;
            const int e = ((kr >> 3) << 1) | xel;
            const int lanei = (kr & 7) * 4 + xqc;
            float q0 = 0.f, q1 = 0.f, q2 = 0.f, q3 = 0.f;
            #pragma unroll
            for (int ksx = 0; ksx < 4; ++ksx) {
                const float* sl = xch + ((ksx * 2 + xnh) * 32 + lanei) * 65 + xj * 4 + e;
                q0 += sl[0]; q1 += sl[16]; q2 += sl[32]; q3 += sl[48];
            }
            float r = 1.f / (1.f + __expf(-(q0 + brv[r2])));
            float z = 1.f / (1.f + __expf(-(q1 + bzv[r2])));
            float n = tanhf(q3 + binv[r2] + r * (q2 + bhnv[r2]));
            float hv = (1.f - z) * n + z * hprev[r2];
            hprev[r2] = hv;
            hdst[(size_t)(hid0 + kr) * BB + b0 + bcol] = hv;
            if (t == TT - 1)
                out[(size_t)TT * BB * OO + (size_t)(b0 + bcol) * HH + hid0 + kr] = hv;
        }
        if (t > 0 && tid < 128) {
            int o2 = tid >> 6, b = tid & 63;
            float y = yx[o2 * 64 + b] + yx[(2 + o2) * 64 + b] +
                      yx[(4 + o2) * 64 + b] + yx[(6 + o2) * 64 + b] + yb;
            out[((size_t)(t - 1) * BB + b0 + b) * OO + orow0 + o2] = y;
        }

        // grid barrier (CG-style: release-red arrive, acquire-ld poll)
        __syncthreads();
        if (tid == 0) {
            asm volatile("red.release.gpu.add.u32 [%0], %1;" :: "l"(&g_count), "r"(1u) : "memory");
            unsigned tgt = (unsigned)NBLK * (unsigned)(t + 1), v;
            do {
                asm volatile("ld.acquire.gpu.u32 %0, [%1];" : "=r"(v) : "l"(&g_count) : "memory");
            } while (v < tgt);
        }
        __syncthreads();
    }

    // final y[1023] from h[1024] (slot 0), full fp32 via L2
    {
        const float* hsrc = g_hbuf[TT & 1];
        float yp0 = 0.f, yp1 = 0.f;
        const int kbeg = (tid >> 6) * 128;
        for (int k = kbeg; k < kbeg + 128; ++k) {
            float hv = hsrc[(size_t)k * BB + b0 + bcol];
            yp0 = fmaf(hv, wo[k], yp0);
            yp1 = fmaf(hv, wo[512 + k], yp1);
        }
        yx[((tid >> 6) * 2 + 0) * 64 + bcol] = yp0;
        yx[((tid >> 6) * 2 + 1) * 64 + bcol] = yp1;
        __syncthreads();
        if (tid < 128) {
            int o2 = tid >> 6, b = tid & 63;
            float y = yx[o2 * 64 + b] + yx[(2 + o2) * 64 + b] +
                      yx[(4 + o2) * 64 + b] + yx[(6 + o2) * 64 + b] + yb;
            out[((size_t)(TT - 1) * BB + b0 + b) * OO + orow0 + o2] = y;
        }
    }
}

extern "C" void kernel_launch(void* const* d_in, const int* in_sizes, int n_in,
                              void* d_out, int out_size) {
    const float* code_vec = (const float*)d_in[0];
    const float* target   = (const float*)d_in[1];
    const float* w_ih     = (const float*)d_in[2];
    const float* w_hh     = (const float*)d_in[3];
    const float* b_ih     = (const float*)d_in[4];
    const float* b_hh     = (const float*)d_in[5];
    const float* w_out    = (const float*)d_in[6];
    const float* b_out    = (const float*)d_in[7];
    float* out = (float*)d_out;

    const size_t smem_step = SM_TOTF * sizeof(float);   // 208896 B
    cudaFuncSetAttribute(gru_persistent, cudaFuncAttributeMaxDynamicSharedMemorySize, (int)smem_step);

    prep_h0<<<(HH * BB + 255) / 256, 256>>>(code_vec);
    prep_x<<<TT, 256>>>(target);
    // dummies shift ncu -s 5 capture onto gru_persistent
    dummy_k<<<1, 32>>>(0);
    dummy_k<<<1, 32>>>(0);
    dummy_k<<<1, 32>>>(0);
    gru_persistent<<<NBLK, NTHR, smem_step>>>(out, w_ih, w_hh, b_ih, b_hh, w_out, b_out);
}

// round 7
// speedup vs baseline: 1.4018x; 1.0682x over previous
#include <cuda_runtime.h>
#include <cstdint>
#include <cstddef>

#define TT 1024
#define BB 256
#define HH 512
#define OO 64
#define NBLK 128
#define NTHR 256

__device__ float g_hbuf[2][HH * BB];    // rotating h slots [k][b] (1 MB, L2-resident)
__device__ float g_xT[TT * OO * BB];    // [t][o][b], tf32-rounded
__device__ unsigned g_cnt4[4];          // per-batch-group barrier counters

__device__ __forceinline__ float tf32r(float x) {
    uint32_t u;
    asm("cvt.rna.tf32.f32 %0, %1;" : "=r"(u) : "f"(x));
    return __uint_as_float(u);
}

__device__ __forceinline__ void mma8(float* d, const float4 a4, float b0, float b1) {
    uint32_t A0 = __float_as_uint(a4.x), A1 = __float_as_uint(a4.y);
    uint32_t A2 = __float_as_uint(a4.z), A3 = __float_as_uint(a4.w);
    uint32_t B0 = __float_as_uint(b0), B1 = __float_as_uint(b1);
    asm volatile(
        "mma.sync.aligned.m16n8k8.row.col.f32.tf32.tf32.f32 "
        "{%0,%1,%2,%3}, {%4,%5,%6,%7}, {%8,%9}, {%0,%1,%2,%3};\n"
        : "+f"(d[0]), "+f"(d[1]), "+f"(d[2]), "+f"(d[3])
        : "r"(A0), "r"(A1), "r"(A2), "r"(A3), "r"(B0), "r"(B1));
}

__device__ __forceinline__ void cpa16(uint32_t dst, const void* src) {
    asm volatile("cp.async.ca.shared.global [%0], [%1], 16;\n" :: "r"(dst), "l"(src));
}

__global__ void prep_h0(const float* __restrict__ code_vec) {
    if (blockIdx.x == 0 && threadIdx.x < 4) g_cnt4[threadIdx.x] = 0u;
    int idx = blockIdx.x * 256 + threadIdx.x;
    if (idx < HH * BB) {
        int k = idx >> 8, b = idx & 255;
        g_hbuf[0][k * BB + b] = code_vec[b * HH + k];
    }
}

__global__ void prep_x(const float* __restrict__ target) {
    int t = blockIdx.x;
    for (int i = threadIdx.x; i < OO * BB; i += 256) {
        int o = i >> 8, b = i & 255;
        float v = (t == 0) ? 0.f : target[((size_t)(t - 1) * BB + b) * OO + o];
        g_xT[(size_t)t * OO * BB + i] = tf32r(v);
    }
}

__global__ void dummy_k(int x) { if (x == 12345 && threadIdx.x > 1024) g_cnt4[0] = 1; }

// SMEM floats: Wp 27648 | buf 2x[128][72]=18432 (xch overlays: 256*65=16640)
//            | sx [64][72]=4608 | woP [72][32]float2=4608 | yx [8][2][32]=512
#define SM_BUF 27648
#define SM_SX  46080
#define SM_WOP 50688
#define SM_YX  55296
#define SM_TOTF 55808   // 223232 B

__global__ __launch_bounds__(NTHR, 1) void gru_persistent(
    float* __restrict__ out,
    const float* __restrict__ w_ih, const float* __restrict__ w_hh,
    const float* __restrict__ b_ih, const float* __restrict__ b_hh,
    const float* __restrict__ w_out, const float* __restrict__ b_out) {
    extern __shared__ float sm[];
    float4* Wp4 = reinterpret_cast<float4*>(sm);
    float* buf = sm + SM_BUF;
    float* sx = sm + SM_SX;
    float2* woP = reinterpret_cast<float2*>(sm + SM_WOP);
    float* yx = sm + SM_YX;
    float* xch = buf;

    const int tid = threadIdx.x;
    const int mg = blockIdx.x & 31;
    const int bg = blockIdx.x >> 5;
    const int hid0 = mg * 16;
    const int b0 = bg * 64;
    const int lane = tid & 31, w = tid >> 5;
    const int ks = w >> 1, nh = w & 1;      // 4 K-slices x 2 n-halves
    const int qr = lane >> 2, qc = lane & 3;
    const int n0 = nh * 32;
    const int orow0 = mg * 2;

    const uint32_t smem_b = (uint32_t)__cvta_generic_to_shared(sm);
    const uint32_t buf_b = smem_b + SM_BUF * 4u;
    const uint32_t sx_b = smem_b + SM_SX * 4u;

    // pack gate weights into A-fragment layout (validated R1/R3/R5/R6)
    for (int idx = tid; idx < 72 * 96; idx += NTHR) {
        int kstep = idx / 96, r = idx % 96;
        int g = r >> 5, ln = r & 31;
        int lqr = ln >> 2, lqc = ln & 3;
        int row0 = g * HH + hid0 + lqr;
        int c0 = kstep * 8 + lqc, c1 = c0 + 4;
        float4 v;
        v.x = tf32r(c0 < HH ? w_hh[(size_t)row0 * HH + c0] : w_ih[(size_t)row0 * OO + c0 - HH]);
        v.y = tf32r(c0 < HH ? w_hh[(size_t)(row0 + 8) * HH + c0] : w_ih[(size_t)(row0 + 8) * OO + c0 - HH]);
        v.z = tf32r(c1 < HH ? w_hh[(size_t)row0 * HH + c1] : w_ih[(size_t)row0 * OO + c1 - HH]);
        v.w = tf32r(c1 < HH ? w_hh[(size_t)(row0 + 8) * HH + c1] : w_ih[(size_t)(row0 + 8) * OO + c1 - HH]);
        Wp4[idx] = v;
    }
    // pack y A-fragments: rows {w_out[orow0], w_out[orow0+1], 0 x14}, h-ksteps only
    for (int idx = tid; idx < 72 * 32; idx += NTHR) {
        int kstep = idx >> 5, ln = idx & 31;
        int lqr = ln >> 2, lqc = ln & 3;
        float2 v = make_float2(0.f, 0.f);
        if (kstep < 64 && lqr < 2) {
            int c0 = kstep * 8 + lqc;
            v.x = tf32r(w_out[(size_t)(orow0 + lqr) * HH + c0]);
            v.y = tf32r(w_out[(size_t)(orow0 + lqr) * HH + c0 + 4]);
        }
        woP[idx] = v;
    }

    const int krb = tid >> 6, bcol = tid & 63;
    float brv[4], bzv[4], binv[4], bhnv[4];
    #pragma unroll
    for (int r2 = 0; r2 < 4; ++r2) {
        int u = hid0 + krb + 4 * r2;
        brv[r2] = b_ih[u] + b_hh[u];
        bzv[r2] = b_ih[HH + u] + b_hh[HH + u];
        binv[r2] = b_ih[2 * HH + u];
        bhnv[r2] = b_hh[2 * HH + u];
    }
    const int xnh = bcol >> 5, xj = (bcol & 31) >> 3, xqc = (bcol & 7) >> 1, xel = bcol & 1;
    const float yb = (tid < 128) ? b_out[orow0 + (tid >> 6)] : 0.f;

    float hprev[4];
    #pragma unroll
    for (int r2 = 0; r2 < 4; ++r2)
        hprev[r2] = g_hbuf[0][(size_t)(hid0 + krb + 4 * r2) * BB + b0 + bcol];

    for (int t = 0; t < TT; ++t) {
        const float* hsrc = g_hbuf[t & 1];
        const float* xsrc = g_xT + (size_t)t * OO * BB;

        #pragma unroll
        for (int j = 0; j < 8; ++j) {
            int idx = j * NTHR + tid;
            int row = idx >> 4, c4 = (idx & 15) << 2;
            cpa16(buf_b + (uint32_t)((row * 72 + c4) * 4), hsrc + (size_t)row * BB + b0 + c4);
        }
        #pragma unroll
        for (int j = 0; j < 4; ++j) {
            int idx = j * NTHR + tid;
            int row = idx >> 4, c4 = (idx & 15) << 2;
            cpa16(sx_b + (uint32_t)((row * 72 + c4) * 4), xsrc + (size_t)row * BB + b0 + c4);
        }
        asm volatile("cp.async.commit_group;\n");

        float acc[3][4][4] = {}, accX[4][4] = {}, accY[4][4] = {};

        #pragma unroll
        for (int s = 0; s < 4; ++s) {
            asm volatile("cp.async.wait_group 0;\n");
            __syncthreads();
            if (s < 3) {
                const float* src = hsrc + (size_t)(128 * (s + 1)) * BB + b0;
                uint32_t dstb = buf_b + (uint32_t)(((s + 1) & 1) * 9216 * 4);
                #pragma unroll
                for (int j = 0; j < 8; ++j) {
                    int idx = j * NTHR + tid;
                    int row = idx >> 4, c4 = (idx & 15) << 2;
                    cpa16(dstb + (uint32_t)((row * 72 + c4) * 4), src + (size_t)row * BB + c4);
                }
                asm volatile("cp.async.commit_group;\n");
            }
            const float* bs = buf + (s & 1) * 9216;
            #pragma unroll
            for (int c = 0; c < 4; ++c) {
                const int gk = s * 16 + ks * 4 + c;
                const int kk = (ks * 4 + c) * 8;
                float bf0[4], bf1[4];
                #pragma unroll
                for (int j = 0; j < 4; ++j) {
                    bf0[j] = tf32r(bs[(kk + qc) * 72 + n0 + j * 8 + qr]);
                    bf1[j] = tf32r(bs[(kk + 4 + qc) * 72 + n0 + j * 8 + qr]);
                }
                #pragma unroll
                for (int g = 0; g < 3; ++g) {
                    float4 a4 = Wp4[(gk * 3 + g) * 32 + lane];
                    #pragma unroll
                    for (int j = 0; j < 4; ++j) mma8(acc[g][j], a4, bf0[j], bf1[j]);
                }
                float2 ay2 = woP[gk * 32 + lane];
                float4 ay = make_float4(ay2.x, 0.f, ay2.y, 0.f);
                #pragma unroll
                for (int j = 0; j < 4; ++j) mma8(accY[j], ay, bf0[j], bf1[j]);
            }
        }
        // x-path (pre-rounded); gate-n x-part separate; no y contribution
        #pragma unroll
        for (int c2 = 0; c2 < 2; ++c2) {
            const int gk = 64 + ks * 2 + c2;
            const int kk = (ks * 2 + c2) * 8;
            float bf0[4], bf1[4];
            #pragma unroll
            for (int j = 0; j < 4; ++j) {
                bf0[j] = sx[(kk + qc) * 72 + n0 + j * 8 + qr];
                bf1[j] = sx[(kk + 4 + qc) * 72 + n0 + j * 8 + qr];
            }
            float4 a0 = Wp4[(gk * 3 + 0) * 32 + lane];
            float4 a1 = Wp4[(gk * 3 + 1) * 32 + lane];
            float4 a2 = Wp4[(gk * 3 + 2) * 32 + lane];
            #pragma unroll
            for (int j = 0; j < 4; ++j) {
                mma8(acc[0][j], a0, bf0[j], bf1[j]);
                mma8(acc[1][j], a1, bf0[j], bf1[j]);
                mma8(accX[j], a2, bf0[j], bf1[j]);
            }
        }

        __syncthreads();  // done reading buf/sx; overlay exchange
        {
            float* slot = xch + tid * 65;
            #pragma unroll
            for (int g = 0; g < 3; ++g)
                #pragma unroll
                for (int j = 0; j < 4; ++j)
                    #pragma unroll
                    for (int e = 0; e < 4; ++e)
                        slot[g * 16 + j * 4 + e] = acc[g][j][e];
            #pragma unroll
            for (int j = 0; j < 4; ++j)
                #pragma unroll
                for (int e = 0; e < 4; ++e)
                    slot[48 + j * 4 + e] = accX[j][e];
        }
        if (qr < 2) {   // y partials: rows 0,1 of accY tiles
            #pragma unroll
            for (int j = 0; j < 4; ++j) {
                yx[(w * 2 + qr) * 32 + j * 8 + qc * 2] = accY[j][0];
                yx[(w * 2 + qr) * 32 + j * 8 + qc * 2 + 1] = accY[j][1];
            }
        }
        __syncthreads();

        float* hdst = g_hbuf[(t + 1) & 1];
        #pragma unroll
        for (int r2 = 0; r2 < 4; ++r2) {
            const int kr = krb + 4 * r2;
            const int e = ((kr >> 3) << 1) | xel;
            const int lanei = (kr & 7) * 4 + xqc;
            float q0 = 0.f, q1 = 0.f, q2 = 0.f, q3 = 0.f;
            #pragma unroll
            for (int ksx = 0; ksx < 4; ++ksx) {
                const float* sl = xch + ((ksx * 2 + xnh) * 32 + lanei) * 65 + xj * 4 + e;
                q0 += sl[0]; q1 += sl[16]; q2 += sl[32]; q3 += sl[48];
            }
            float r = 1.f / (1.f + __expf(-(q0 + brv[r2])));
            float z = 1.f / (1.f + __expf(-(q1 + bzv[r2])));
            float n = tanhf(q3 + binv[r2] + r * (q2 + bhnv[r2]));
            float hv = (1.f - z) * n + z * hprev[r2];
            hprev[r2] = hv;
            hdst[(size_t)(hid0 + kr) * BB + b0 + bcol] = hv;
            if (t == TT - 1)
                out[(size_t)TT * BB * OO + (size_t)(b0 + bcol) * HH + hid0 + kr] = hv;
        }
        if (t > 0 && tid < 128) {
            int o2 = tid >> 6, b = tid & 63;
            int bn = b >> 5, bl = b & 31;
            float y = yb;
            #pragma unroll
            for (int ksx = 0; ksx < 4; ++ksx)
                y += yx[((ksx * 2 + bn) * 2 + o2) * 32 + bl];
            out[((size_t)(t - 1) * BB + b0 + b) * OO + orow0 + o2] = y;
        }

        // per-batch-group grid barrier (32 blocks each; groups independent)
        __syncthreads();
        if (tid == 0) {
            asm volatile("red.release.gpu.add.u32 [%0], %1;" :: "l"(&g_cnt4[bg]), "r"(1u) : "memory");
            unsigned tgt = 32u * (unsigned)(t + 1), v;
            do {
                asm volatile("ld.acquire.gpu.u32 %0, [%1];" : "=r"(v) : "l"(&g_cnt4[bg]) : "memory");
            } while (v < tgt);
        }
        __syncthreads();
    }

    // final y[1023] from h[1024], fp32 via L2 (once)
    {
        const float* hsrc = g_hbuf[TT & 1];
        float yp0 = 0.f, yp1 = 0.f;
        const int kbeg = (tid >> 6) * 128;
        for (int k = kbeg; k < kbeg + 128; ++k) {
            float hv = hsrc[(size_t)k * BB + b0 + bcol];
            yp0 = fmaf(hv, w_out[(size_t)orow0 * HH + k], yp0);
            yp1 = fmaf(hv, w_out[(size_t)(orow0 + 1) * HH + k], yp1);
        }
        __syncthreads();
        yx[((tid >> 6) * 2 + 0) * 64 + bcol] = yp0;
        yx[((tid >> 6) * 2 + 1) * 64 + bcol] = yp1;
        __syncthreads();
        if (tid < 128) {
            int o2 = tid >> 6, b = tid & 63;
            float y = yx[o2 * 64 + b] + yx[(2 + o2) * 64 + b] +
                      yx[(4 + o2) * 64 + b] + yx[(6 + o2) * 64 + b] + yb;
            out[((size_t)(TT - 1) * BB + b0 + b) * OO + orow0 + o2] = y;
        }
    }
}

extern "C" void kernel_launch(void* const* d_in, const int* in_sizes, int n_in,
                              void* d_out, int out_size) {
    const float* code_vec = (const float*)d_in[0];
    const float* target   = (const float*)d_in[1];
    const float* w_ih     = (const float*)d_in[2];
    const float* w_hh     = (const float*)d_in[3];
    const float* b_ih     = (const float*)d_in[4];
    const float* b_hh     = (const float*)d_in[5];
    const float* w_out    = (const float*)d_in[6];
    const float* b_out    = (const float*)d_in[7];
    float* out = (float*)d_out;

    const size_t smem_step = SM_TOTF * sizeof(float);   // 223232 B
    cudaFuncSetAttribute(gru_persistent, cudaFuncAttributeMaxDynamicSharedMemorySize, (int)smem_step);

    prep_h0<<<(HH * BB + 255) / 256, 256>>>(code_vec);       // idx 0
    prep_x<<<TT, 256>>>(target);                             // idx 1
    dummy_k<<<1, 32>>>(0);                                   // idx 2
    gru_persistent<<<NBLK, NTHR, smem_step>>>(out, w_ih, w_hh, b_ih, b_hh, w_out, b_out);  // idx 3 <- ncu
}

// round 8
// speedup vs baseline: 1.4227x; 1.0149x over previous
#include <cuda_runtime.h>
#include <cstdint>
#include <cstddef>

#define TT 1024
#define BB 256
#define HH 512
#define OO 64
#define NBLK 128
#define NTHR 512

__device__ float g_hbuf[2][HH * BB];    // rotating h slots [k][b]
__device__ float g_xT[TT * OO * BB];    // [t][o][b], tf32-rounded
__device__ unsigned g_cnt4[4];

__device__ __forceinline__ float tf32r(float x) {
    uint32_t u;
    asm("cvt.rna.tf32.f32 %0, %1;" : "=r"(u) : "f"(x));
    return __uint_as_float(u);
}

__device__ __forceinline__ void mma8(float* d, const float4 a4, float b0, float b1) {
    uint32_t A0 = __float_as_uint(a4.x), A1 = __float_as_uint(a4.y);
    uint32_t A2 = __float_as_uint(a4.z), A3 = __float_as_uint(a4.w);
    uint32_t B0 = __float_as_uint(b0), B1 = __float_as_uint(b1);
    asm volatile(
        "mma.sync.aligned.m16n8k8.row.col.f32.tf32.tf32.f32 "
        "{%0,%1,%2,%3}, {%4,%5,%6,%7}, {%8,%9}, {%0,%1,%2,%3};\n"
        : "+f"(d[0]), "+f"(d[1]), "+f"(d[2]), "+f"(d[3])
        : "r"(A0), "r"(A1), "r"(A2), "r"(A3), "r"(B0), "r"(B1));
}

__device__ __forceinline__ void cpa16(uint32_t dst, const void* src) {
    asm volatile("cp.async.ca.shared.global [%0], [%1], 16;\n" :: "r"(dst), "l"(src));
}

__global__ void prep_h0(const float* __restrict__ code_vec) {
    if (blockIdx.x == 0 && threadIdx.x < 4) g_cnt4[threadIdx.x] = 0u;
    int idx = blockIdx.x * 256 + threadIdx.x;
    if (idx < HH * BB) {
        int k = idx >> 8, b = idx & 255;
        g_hbuf[0][k * BB + b] = code_vec[b * HH + k];
    }
}

__global__ void prep_x(const float* __restrict__ target) {
    int t = blockIdx.x;
    for (int i = threadIdx.x; i < OO * BB; i += 256) {
        int o = i >> 8, b = i & 255;
        float v = (t == 0) ? 0.f : target[((size_t)(t - 1) * BB + b) * OO + o];
        g_xT[(size_t)t * OO * BB + i] = tf32r(v);
    }
}

__global__ void dummy_k(int x) { if (x == 12345 && threadIdx.x > 1024) g_cnt4[0] = 1; }

// SMEM floats: Wp 27648 | buf 2x[128][72]=18432 (xch 16384 overlays)
//            | sx [64][72]=4608 | woP [72][32]float2=4608 | yx 512
#define SM_BUF 27648
#define SM_SX  46080
#define SM_WOP 50688
#define SM_YX  55296
#define SM_TOTF 55808   // 223232 B

__global__ __launch_bounds__(NTHR, 1) void gru_persistent(
    float* __restrict__ out,
    const float* __restrict__ w_ih, const float* __restrict__ w_hh,
    const float* __restrict__ b_ih, const float* __restrict__ b_hh,
    const float* __restrict__ w_out, const float* __restrict__ b_out) {
    extern __shared__ float sm[];
    float4* Wp4 = reinterpret_cast<float4*>(sm);
    float* buf = sm + SM_BUF;
    float* sx = sm + SM_SX;
    float2* woP = reinterpret_cast<float2*>(sm + SM_WOP);
    float* yx = sm + SM_YX;
    float* xch = buf;

    const int tid = threadIdx.x;
    const int mg = blockIdx.x & 31;
    const int bg = blockIdx.x >> 5;
    const int hid0 = mg * 16;
    const int b0 = bg * 64;
    const int lane = tid & 31, w = tid >> 5;
    const int ks = w >> 2, nq = w & 3;      // 4 K-slices x 4 n-quarters (16 cols)
    const int qr = lane >> 2, qc = lane & 3;
    const int n0 = nq * 16;
    const int orow0 = mg * 2;
    const int wb_w = nq >> 1, hi_w = nq & 1;
    // writer exchange base terms: addr = (2ks+wb)*2048 + g*512 + rh*256 + qr*32 + bank
    const int wXbase = (ks * 2 + wb_w) * 2048 + qr * 32;
    const int wbank0 = 4 * qr + qc + 16 * hi_w;   // + 8j + 4elow, &31

    const uint32_t smem_b = (uint32_t)__cvta_generic_to_shared(sm);
    const uint32_t buf_b = smem_b + SM_BUF * 4u;
    const uint32_t sx_b = smem_b + SM_SX * 4u;

    // pack gate weights into A-fragment layout (validated R1/R3/R5-R7)
    for (int idx = tid; idx < 72 * 96; idx += NTHR) {
        int kstep = idx / 96, r = idx % 96;
        int g = r >> 5, ln = r & 31;
        int lqr = ln >> 2, lqc = ln & 3;
        int row0 = g * HH + hid0 + lqr;
        int c0 = kstep * 8 + lqc, c1 = c0 + 4;
        float4 v;
        v.x = tf32r(c0 < HH ? w_hh[(size_t)row0 * HH + c0] : w_ih[(size_t)row0 * OO + c0 - HH]);
        v.y = tf32r(c0 < HH ? w_hh[(size_t)(row0 + 8) * HH + c0] : w_ih[(size_t)(row0 + 8) * OO + c0 - HH]);
        v.z = tf32r(c1 < HH ? w_hh[(size_t)row0 * HH + c1] : w_ih[(size_t)row0 * OO + c1 - HH]);
        v.w = tf32r(c1 < HH ? w_hh[(size_t)(row0 + 8) * HH + c1] : w_ih[(size_t)(row0 + 8) * OO + c1 - HH]);
        Wp4[idx] = v;
    }
    // pack y A-fragments: rows {w_out[orow0], w_out[orow0+1], 0...}, h-ksteps only
    for (int idx = tid; idx < 72 * 32; idx += NTHR) {
        int kstep = idx >> 5, ln = idx & 31;
        int lqr = ln >> 2, lqc = ln & 3;
        float2 v = make_float2(0.f, 0.f);
        if (kstep < 64 && lqr < 2) {
            int c0 = kstep * 8 + lqc;
            v.x = tf32r(w_out[(size_t)(orow0 + lqr) * HH + c0]);
            v.y = tf32r(w_out[(size_t)(orow0 + lqr) * HH + c0 + 4]);
        }
        woP[idx] = v;
    }

    // epilogue mapping: thread -> rows (krb, krb+8), col bcol
    const int krb = tid >> 6, bcol = tid & 63;
    float brv[2], bzv[2], binv[2], bhnv[2];
    #pragma unroll
    for (int r2 = 0; r2 < 2; ++r2) {
        int u = hid0 + krb + 8 * r2;
        brv[r2] = b_ih[u] + b_hh[u];
        bzv[r2] = b_ih[HH + u] + b_hh[HH + u];
        binv[r2] = b_ih[2 * HH + u];
        bhnv[r2] = b_hh[2 * HH + u];
    }
    // reader exchange terms
    const int hir = (bcol >> 4) & 1, wbr = bcol >> 5, jr = (bcol >> 3) & 1;
    const int qcr = (bcol & 7) >> 1, er = bcol & 1;
    const int rbank = (4 * krb + qcr + 8 * jr + 4 * er + 16 * hir) & 31;
    const int rbase = wbr * 2048 + krb * 32 + rbank;
    const float yb = (tid < 128) ? b_out[orow0 + (tid >> 6)] : 0.f;
    const int ynq = bcol >> 4, ylo = bcol & 15;

    float hprev[2];
    #pragma unroll
    for (int r2 = 0; r2 < 2; ++r2)
        hprev[r2] = g_hbuf[0][(size_t)(hid0 + krb + 8 * r2) * BB + b0 + bcol];

    for (int t = 0; t < TT; ++t) {
        const float* hsrc = g_hbuf[t & 1];
        const float* xsrc = g_xT + (size_t)t * OO * BB;

        #pragma unroll
        for (int j = 0; j < 4; ++j) {
            int idx = j * NTHR + tid;
            int row = idx >> 4, c4 = (idx & 15) << 2;
            cpa16(buf_b + (uint32_t)((row * 72 + c4) * 4), hsrc + (size_t)row * BB + b0 + c4);
        }
        #pragma unroll
        for (int j = 0; j < 2; ++j) {
            int idx = j * NTHR + tid;
            int row = idx >> 4, c4 = (idx & 15) << 2;
            cpa16(sx_b + (uint32_t)((row * 72 + c4) * 4), xsrc + (size_t)row * BB + b0 + c4);
        }
        asm volatile("cp.async.commit_group;\n");

        float acc[3][2][4] = {}, accX[2][4] = {}, accY[2][4] = {};

        #pragma unroll
        for (int s = 0; s < 4; ++s) {
            asm volatile("cp.async.wait_group 0;\n");
            __syncthreads();
            if (s < 3) {
                const float* src = hsrc + (size_t)(128 * (s + 1)) * BB + b0;
                uint32_t dstb = buf_b + (uint32_t)(((s + 1) & 1) * 9216 * 4);
                #pragma unroll
                for (int j = 0; j < 4; ++j) {
                    int idx = j * NTHR + tid;
                    int row = idx >> 4, c4 = (idx & 15) << 2;
                    cpa16(dstb + (uint32_t)((row * 72 + c4) * 4), src + (size_t)row * BB + c4);
                }
                asm volatile("cp.async.commit_group;\n");
            }
            const float* bs = buf + (s & 1) * 9216;
            #pragma unroll
            for (int c = 0; c < 4; ++c) {
                const int gk = s * 16 + ks * 4 + c;
                const int kk = (ks * 4 + c) * 8;
                float bf0[2], bf1[2];
                #pragma unroll
                for (int j = 0; j < 2; ++j) {
                    bf0[j] = tf32r(bs[(kk + qc) * 72 + n0 + j * 8 + qr]);
                    bf1[j] = tf32r(bs[(kk + 4 + qc) * 72 + n0 + j * 8 + qr]);
                }
                #pragma unroll
                for (int g = 0; g < 3; ++g) {
                    float4 a4 = Wp4[(gk * 3 + g) * 32 + lane];
                    mma8(acc[g][0], a4, bf0[0], bf1[0]);
                    mma8(acc[g][1], a4, bf0[1], bf1[1]);
                }
                float2 ay2 = woP[gk * 32 + lane];
                float4 ay = make_float4(ay2.x, 0.f, ay2.y, 0.f);
                mma8(accY[0], ay, bf0[0], bf1[0]);
                mma8(accY[1], ay, bf0[1], bf1[1]);
            }
        }
        // x-path (pre-rounded); gate-n x-part separate; no y contribution
        #pragma unroll
        for (int c2 = 0; c2 < 2; ++c2) {
            const int gk = 64 + ks * 2 + c2;
            const int kk = (ks * 2 + c2) * 8;
            float bf0[2], bf1[2];
            #pragma unroll
            for (int j = 0; j < 2; ++j) {
                bf0[j] = sx[(kk + qc) * 72 + n0 + j * 8 + qr];
                bf1[j] = sx[(kk + 4 + qc) * 72 + n0 + j * 8 + qr];
            }
            float4 a0 = Wp4[(gk * 3 + 0) * 32 + lane];
            float4 a1 = Wp4[(gk * 3 + 1) * 32 + lane];
            float4 a2 = Wp4[(gk * 3 + 2) * 32 + lane];
            #pragma unroll
            for (int j = 0; j < 2; ++j) {
                mma8(acc[0][j], a0, bf0[j], bf1[j]);
                mma8(acc[1][j], a1, bf0[j], bf1[j]);
                mma8(accX[j], a2, bf0[j], bf1[j]);
            }
        }

        __syncthreads();  // done reading buf/sx; overlay exchange
        // conflict-free exchange: addr = (2ks+wb)*2048 + g*512 + rh*256 + qr*32 + bank
        #pragma unroll
        for (int g = 0; g < 4; ++g)
            #pragma unroll
            for (int rh = 0; rh < 2; ++rh)
                #pragma unroll
                for (int j = 0; j < 2; ++j)
                    #pragma unroll
                    for (int el = 0; el < 2; ++el) {
                        float v = (g < 3) ? acc[g][j][rh * 2 + el] : accX[j][rh * 2 + el];
                        xch[wXbase + g * 512 + rh * 256 + ((wbank0 + 8 * j + 4 * el) & 31)] = v;
                    }
        if (qr < 2) {
            #pragma unroll
            for (int j = 0; j < 2; ++j) {
                yx[(w * 2 + qr) * 16 + j * 8 + qc * 2] = accY[j][0];
                yx[(w * 2 + qr) * 16 + j * 8 + qc * 2 + 1] = accY[j][1];
            }
        }
        __syncthreads();

        float* hdst = g_hbuf[(t + 1) & 1];
        #pragma unroll
        for (int r2 = 0; r2 < 2; ++r2) {
            float q0 = 0.f, q1 = 0.f, q2s = 0.f, q3 = 0.f;
            #pragma unroll
            for (int ksx = 0; ksx < 4; ++ksx) {
                const float* sl = xch + rbase + ksx * 4096 + r2 * 256;
                q0 += sl[0]; q1 += sl[512]; q2s += sl[1024]; q3 += sl[1536];
            }
            float r = 1.f / (1.f + __expf(-(q0 + brv[r2])));
            float z = 1.f / (1.f + __expf(-(q1 + bzv[r2])));
            float n = tanhf(q3 + binv[r2] + r * (q2s + bhnv[r2]));
            float hv = (1.f - z) * n + z * hprev[r2];
            hprev[r2] = hv;
            hdst[(size_t)(hid0 + krb + 8 * r2) * BB + b0 + bcol] = hv;
            if (t == TT - 1)
                out[(size_t)TT * BB * OO + (size_t)(b0 + bcol) * HH + hid0 + krb + 8 * r2] = hv;
        }
        if (t > 0 && tid < 128) {
            int o2 = tid >> 6, b = tid & 63;
            float y = yb;
            #pragma unroll
            for (int ksx = 0; ksx < 4; ++ksx)
                y += yx[((ksx * 4 + ynq) * 2 + o2) * 16 + ylo];
            out[((size_t)(t - 1) * BB + b0 + b) * OO + orow0 + o2] = y;
        }

        __syncthreads();
        if (tid == 0) {
            asm volatile("red.release.gpu.add.u32 [%0], %1;" :: "l"(&g_cnt4[bg]), "r"(1u) : "memory");
            unsigned tgt = 32u * (unsigned)(t + 1), v;
            do {
                asm volatile("ld.acquire.gpu.u32 %0, [%1];" : "=r"(v) : "l"(&g_cnt4[bg]) : "memory");
            } while (v < tgt);
        }
        __syncthreads();
    }

    // final y[1023] from h[1024], fp32 via L2
    {
        const float* hsrc = g_hbuf[TT & 1];
        int o2 = (tid >> 6) & 1, q = tid >> 7;
        const int kbeg = q * 128;
        float yp = 0.f;
        for (int k = kbeg; k < kbeg + 128; ++k)
            yp = fmaf(hsrc[(size_t)k * BB + b0 + bcol], w_out[(size_t)(orow0 + o2) * HH + k], yp);
        __syncthreads();
        yx[(q * 2 + o2) * 64 + bcol] = yp;
        __syncthreads();
        if (tid < 128) {
            int oo2 = tid >> 6, b = tid & 63;
            float y = yx[oo2 * 64 + b] + yx[(2 + oo2) * 64 + b] +
                      yx[(4 + oo2) * 64 + b] + yx[(6 + oo2) * 64 + b] + yb;
            out[((size_t)(TT - 1) * BB + b0 + b) * OO + orow0 + oo2] = y;
        }
    }
}

extern "C" void kernel_launch(void* const* d_in, const int* in_sizes, int n_in,
                              void* d_out, int out_size) {
    const float* code_vec = (const float*)d_in[0];
    const float* target   = (const float*)d_in[1];
    const float* w_ih     = (const float*)d_in[2];
    const float* w_hh     = (const float*)d_in[3];
    const float* b_ih     = (const float*)d_in[4];
    const float* b_hh     = (const float*)d_in[5];
    const float* w_out    = (const float*)d_in[6];
    const float* b_out    = (const float*)d_in[7];
    float* out = (float*)d_out;

    const size_t smem_step = SM_TOTF * sizeof(float);   // 223232 B
    cudaFuncSetAttribute(gru_persistent, cudaFuncAttributeMaxDynamicSharedMemorySize, (int)smem_step);

    prep_h0<<<(HH * BB + 255) / 256, 256>>>(code_vec);       // idx 0
    prep_x<<<TT, 256>>>(target);                             // idx 1
    dummy_k<<<1, 32>>>(0);                                   // idx 2
    gru_persistent<<<NBLK, NTHR, smem_step>>>(out, w_ih, w_hh, b_ih, b_hh, w_out, b_out);  // idx 3 <- ncu
}